// round 3
// baseline (speedup 1.0000x reference)
#include <cuda_runtime.h>
#include <math.h>

#define BATCH 4
#define SEQ   2048
#define DIM   2048

#define BM 128
#define BN 128
#define BKK 16
#define TM 8
#define TN 8
#define NTHR 256

// Scratch (allocation-free rule: static __device__ arrays)
__device__ float g_Q[BATCH * SEQ * DIM];
__device__ float g_K[BATCH * SEQ * DIM];
__device__ float g_V[BATCH * SEQ * DIM];
__device__ float g_E[BATCH * SEQ * SEQ];
__device__ float g_Z[BATCH * SEQ];

// ---------------------------------------------------------------------------
// Shared tile helpers
// ---------------------------------------------------------------------------

// Load a BM x BKK tile of row-major P (leading dim ld), transposed into Sm[k][m].
__device__ __forceinline__ void load_nt_tile(const float* __restrict__ P, int ld, int k0,
                                             float (*Sm)[BM + 4], int tid)
{
#pragma unroll
    for (int l = 0; l < 2; l++) {
        int i = tid + l * NTHR;          // 0..511
        int r = i >> 2;                  // 0..127  (row within tile)
        int c = (i & 3) << 2;            // 0,4,8,12 (col group)
        float4 v = *(const float4*)(P + (size_t)r * ld + k0 + c);
        Sm[c + 0][r] = v.x;
        Sm[c + 1][r] = v.y;
        Sm[c + 2][r] = v.z;
        Sm[c + 3][r] = v.w;
    }
}

// NN load of a BKK x BN tile: Sm[k][n] = P[(k0+k)*ld + n0+n], coalesced along n.
__device__ __forceinline__ void load_nn_tile(const float* __restrict__ P, int ld, int k0,
                                             float (*Sm)[BN + 4], int tid)
{
#pragma unroll
    for (int l = 0; l < 2; l++) {
        int i  = tid + l * NTHR;       // 0..511
        int kr = i >> 5;               // 0..15
        int c  = (i & 31) << 2;        // 0..124 step 4
        *(float4*)&Sm[kr][c] = *(const float4*)(P + (size_t)(k0 + kr) * ld + c);
    }
}

__device__ __forceinline__ void fma_tile(const float (*As)[BM + 4], const float (*Bs)[BN + 4],
                                         int ty, int tx, float (&acc)[TM][TN])
{
#pragma unroll
    for (int kk = 0; kk < BKK; kk++) {
        float a[TM], b[TN];
        *(float4*)&a[0] = *(const float4*)&As[kk][ty * TM];
        *(float4*)&a[4] = *(const float4*)&As[kk][ty * TM + 4];
        *(float4*)&b[0] = *(const float4*)&Bs[kk][tx * TN];
        *(float4*)&b[4] = *(const float4*)&Bs[kk][tx * TN + 4];
#pragma unroll
        for (int i = 0; i < TM; i++)
#pragma unroll
            for (int j = 0; j < TN; j++)
                acc[i][j] = fmaf(a[i], b[j], acc[i][j]);
    }
}

// ---------------------------------------------------------------------------
// 1) QKV projection: C[m,n] = sum_k X[m,k] * W[n,k]   (NT GEMM, double-buffered)
// ---------------------------------------------------------------------------
__global__ __launch_bounds__(NTHR) void qkv_kernel(const float* __restrict__ X,
                                                   const float* __restrict__ Wq,
                                                   const float* __restrict__ Wk,
                                                   const float* __restrict__ Wv)
{
    __shared__ float As[2][BKK][BM + 4];
    __shared__ float Bs[2][BKK][BN + 4];

    const int tid = threadIdx.x;
    const int tx = tid & 15, ty = tid >> 4;
    const int m0 = blockIdx.y * BM, n0 = blockIdx.x * BN;

    const float* W = (blockIdx.z == 0) ? Wq : (blockIdx.z == 1) ? Wk : Wv;
    float* C       = (blockIdx.z == 0) ? g_Q : (blockIdx.z == 1) ? g_K : g_V;

    const float* A  = X + (size_t)m0 * DIM;
    const float* Bp = W + (size_t)n0 * DIM;

    float acc[TM][TN] = {};

    load_nt_tile(A, DIM, 0, As[0], tid);
    load_nt_tile(Bp, DIM, 0, Bs[0], tid);
    __syncthreads();

    int cur = 0;
    for (int k0 = 0; k0 < DIM; k0 += BKK) {
        int nxt = cur ^ 1;
        if (k0 + BKK < DIM) {
            load_nt_tile(A, DIM, k0 + BKK, As[nxt], tid);
            load_nt_tile(Bp, DIM, k0 + BKK, Bs[nxt], tid);
        }
        fma_tile(As[cur], Bs[cur], ty, tx, acc);
        __syncthreads();
        cur = nxt;
    }

#pragma unroll
    for (int i = 0; i < TM; i++) {
        float* c = C + (size_t)(m0 + ty * TM + i) * DIM + n0 + tx * TN;
        *(float4*)c       = make_float4(acc[i][0], acc[i][1], acc[i][2], acc[i][3]);
        *(float4*)(c + 4) = make_float4(acc[i][4], acc[i][5], acc[i][6], acc[i][7]);
    }
}

// ---------------------------------------------------------------------------
// 2) RoPE (HF style) applied in place to g_Q and g_K.
// ---------------------------------------------------------------------------
__global__ void rope_kernel(const float* __restrict__ cosp, const float* __restrict__ sinp)
{
    int idx = blockIdx.x * blockDim.x + threadIdx.x;   // over BATCH*SEQ*(DIM/2)
    int d  = idx & (DIM / 2 - 1);                      // 0..1023
    int bs = idx >> 10;                                // b*SEQ + s
    int s  = bs & (SEQ - 1);

    float c1 = cosp[s * DIM + d];
    float s1 = sinp[s * DIM + d];
    float c2 = cosp[s * DIM + d + DIM / 2];
    float s2 = sinp[s * DIM + d + DIM / 2];

    size_t base = (size_t)bs * DIM;

    float q1 = g_Q[base + d], q2 = g_Q[base + d + DIM / 2];
    g_Q[base + d]           = q1 * c1 - q2 * s1;
    g_Q[base + d + DIM / 2] = q2 * c2 + q1 * s2;

    float k1 = g_K[base + d], k2 = g_K[base + d + DIM / 2];
    g_K[base + d]           = k1 * c1 - k2 * s1;
    g_K[base + d + DIM / 2] = k2 * c2 + k1 * s2;
}

// ---------------------------------------------------------------------------
// 3) Logits: E[b,s,t] = (t<=s) ? exp((q_s.k_t)/sqrt(SEQ)) : 1.0
//    Multiplicative-mask quirk: masked logits are 0 -> exp(0)=1 stays in the
//    softmax numerator/denominator. Blocks strictly above diagonal skip GEMM.
// ---------------------------------------------------------------------------
__global__ __launch_bounds__(NTHR) void logits_kernel()
{
    const int b  = blockIdx.z;
    const int m0 = blockIdx.y * BM, n0 = blockIdx.x * BN;
    const int tid = threadIdx.x;
    const int tx = tid & 15, ty = tid >> 4;

    float* E = g_E + (size_t)b * SEQ * SEQ;

    if (n0 >= m0 + BM) {  // fully masked block -> all ones
        const float4 one4 = make_float4(1.f, 1.f, 1.f, 1.f);
#pragma unroll
        for (int i = 0; i < TM; i++) {
            float* c = E + (size_t)(m0 + ty * TM + i) * SEQ + n0 + tx * TN;
            *(float4*)c       = one4;
            *(float4*)(c + 4) = one4;
        }
        return;
    }

    __shared__ float As[2][BKK][BM + 4];
    __shared__ float Bs[2][BKK][BN + 4];

    const float* Q  = g_Q + (size_t)b * SEQ * DIM + (size_t)m0 * DIM;
    const float* Kp = g_K + (size_t)b * SEQ * DIM + (size_t)n0 * DIM;

    float acc[TM][TN] = {};

    load_nt_tile(Q, DIM, 0, As[0], tid);
    load_nt_tile(Kp, DIM, 0, Bs[0], tid);
    __syncthreads();

    int cur = 0;
    for (int k0 = 0; k0 < DIM; k0 += BKK) {
        int nxt = cur ^ 1;
        if (k0 + BKK < DIM) {
            load_nt_tile(Q, DIM, k0 + BKK, As[nxt], tid);
            load_nt_tile(Kp, DIM, k0 + BKK, Bs[nxt], tid);
        }
        fma_tile(As[cur], Bs[cur], ty, tx, acc);
        __syncthreads();
        cur = nxt;
    }

    const float invsq = 0.022097086912079608f;  // 1/sqrt(2048)
#pragma unroll
    for (int i = 0; i < TM; i++) {
        int r = m0 + ty * TM + i;
        float o[TN];
#pragma unroll
        for (int j = 0; j < TN; j++) {
            int c = n0 + tx * TN + j;
            o[j] = (c <= r) ? __expf(acc[i][j] * invsq) : 1.0f;
        }
        float* cp = E + (size_t)r * SEQ + n0 + tx * TN;
        *(float4*)cp       = *(float4*)&o[0];
        *(float4*)(cp + 4) = *(float4*)&o[4];
    }
}

// ---------------------------------------------------------------------------
// 4) Row sums of E -> g_Z (deterministic block reduction, one block per row)
// ---------------------------------------------------------------------------
__global__ void rowsum_kernel()
{
    int row = blockIdx.x;                      // 0..BATCH*SEQ-1
    const float* e = g_E + (size_t)row * SEQ;

    float s = 0.f;
    for (int t = threadIdx.x; t < SEQ; t += 256) s += e[t];

#pragma unroll
    for (int o = 16; o > 0; o >>= 1) s += __shfl_xor_sync(0xffffffffu, s, o);

    __shared__ float red[8];
    int w = threadIdx.x >> 5, lane = threadIdx.x & 31;
    if (lane == 0) red[w] = s;
    __syncthreads();
    if (threadIdx.x == 0) {
        float t = 0.f;
#pragma unroll
        for (int i = 0; i < 8; i++) t += red[i];
        g_Z[row] = t;
    }
}

// ---------------------------------------------------------------------------
// 5) PV: out[b,s,d] = (sum_t E[b,s,t] * V[b,t,d]) / Z[b,s]   (NN GEMM)
// ---------------------------------------------------------------------------
__global__ __launch_bounds__(NTHR) void pv_kernel(float* __restrict__ out)
{
    const int b  = blockIdx.z;
    const int m0 = blockIdx.y * BM, n0 = blockIdx.x * BN;
    const int tid = threadIdx.x;
    const int tx = tid & 15, ty = tid >> 4;

    __shared__ float As[2][BKK][BM + 4];
    __shared__ float Bs[2][BKK][BN + 4];

    const float* E = g_E + (size_t)b * SEQ * SEQ + (size_t)m0 * SEQ;
    const float* V = g_V + (size_t)b * SEQ * DIM + n0;

    float acc[TM][TN] = {};

    load_nt_tile(E, SEQ, 0, As[0], tid);
    load_nn_tile(V, DIM, 0, Bs[0], tid);
    __syncthreads();

    int cur = 0;
    for (int k0 = 0; k0 < SEQ; k0 += BKK) {
        int nxt = cur ^ 1;
        if (k0 + BKK < SEQ) {
            load_nt_tile(E, SEQ, k0 + BKK, As[nxt], tid);
            load_nn_tile(V, DIM, k0 + BKK, Bs[nxt], tid);
        }
        fma_tile(As[cur], Bs[cur], ty, tx, acc);
        __syncthreads();
        cur = nxt;
    }

#pragma unroll
    for (int i = 0; i < TM; i++) {
        int r = m0 + ty * TM + i;
        float rinv = 1.0f / g_Z[b * SEQ + r];
        float o[TN];
#pragma unroll
        for (int j = 0; j < TN; j++) o[j] = acc[i][j] * rinv;
        float* cp = out + (size_t)b * SEQ * DIM + (size_t)r * DIM + n0 + tx * TN;
        *(float4*)cp       = *(float4*)&o[0];
        *(float4*)(cp + 4) = *(float4*)&o[4];
    }
}

// ---------------------------------------------------------------------------
// Launch: x, cos, sin, Wq, Wk, Wv  ->  out [B,S,D] fp32
// ---------------------------------------------------------------------------
extern "C" void kernel_launch(void* const* d_in, const int* in_sizes, int n_in,
                              void* d_out, int out_size)
{
    const float* x    = (const float*)d_in[0];
    const float* cosp = (const float*)d_in[1];
    const float* sinp = (const float*)d_in[2];
    const float* Wq   = (const float*)d_in[3];
    const float* Wk   = (const float*)d_in[4];
    const float* Wv   = (const float*)d_in[5];
    float* out = (float*)d_out;

    (void)in_sizes; (void)n_in; (void)out_size;

    qkv_kernel<<<dim3(DIM / BN, (BATCH * SEQ) / BM, 3), NTHR>>>(x, Wq, Wk, Wv);
    rope_kernel<<<(BATCH * SEQ * (DIM / 2)) / 256, 256>>>(cosp, sinp);
    logits_kernel<<<dim3(SEQ / BN, SEQ / BM, BATCH), NTHR>>>();
    rowsum_kernel<<<BATCH * SEQ, 256>>>();
    pv_kernel<<<dim3(DIM / BN, SEQ / BM, BATCH), NTHR>>>(out);
}

// round 5
// speedup vs baseline: 2.5880x; 2.5880x over previous
#include <cuda_runtime.h>
#include <cuda_bf16.h>
#include <stdint.h>
#include <math.h>

#define BATCH 4
#define SEQ   2048
#define DIM   2048

#define BK 32
#define PAD_LD 40                         // bf16 per smem row (80B, conflict-free for ldmatrix)
#define MAT_BYTES (128 * PAD_LD * 2)      // 10240 B per 128x32 matrix
#define SMEM_DYN_BYTES (2 * 4 * MAT_BYTES)  // 2 buffers x (Ah,Al,Bh,Bl) = 81920 B

// ===========================================================================
// PTX helpers (sm_80-era: valid under compute_100)
// ===========================================================================
__device__ __forceinline__ uint32_t smem_to_u32(const void* p) {
    uint32_t a;
    asm("{ .reg .u64 t; cvta.to.shared.u64 t, %1; cvt.u32.u64 %0, t; }" : "=r"(a) : "l"(p));
    return a;
}

__device__ __forceinline__ void cp16(uint32_t dst, const void* src) {
    asm volatile("cp.async.ca.shared.global [%0], [%1], 16;" :: "r"(dst), "l"(src) : "memory");
}
#define CP_COMMIT()  asm volatile("cp.async.commit_group;" ::: "memory")
#define CP_WAIT(n)   asm volatile("cp.async.wait_group %0;" :: "n"(n) : "memory")

__device__ __forceinline__ void ldm_x4(uint32_t addr, uint32_t (&r)[4]) {
    asm volatile("ldmatrix.sync.aligned.m8n8.x4.shared.b16 {%0,%1,%2,%3}, [%4];"
                 : "=r"(r[0]), "=r"(r[1]), "=r"(r[2]), "=r"(r[3]) : "r"(addr));
}

__device__ __forceinline__ void mma16816(float (&c)[4], const uint32_t (&a)[4],
                                         uint32_t b0, uint32_t b1) {
    asm volatile("mma.sync.aligned.m16n8k16.row.col.f32.bf16.bf16.f32 "
                 "{%0,%1,%2,%3}, {%4,%5,%6,%7}, {%8,%9}, {%0,%1,%2,%3};"
                 : "+f"(c[0]), "+f"(c[1]), "+f"(c[2]), "+f"(c[3])
                 : "r"(a[0]), "r"(a[1]), "r"(a[2]), "r"(a[3]), "r"(b0), "r"(b1));
}

// ===========================================================================
// Scratch (allocation-free rule: static __device__ arrays)
// ===========================================================================
__device__ float g_Q[BATCH * SEQ * DIM];
__device__ float g_K[BATCH * SEQ * DIM];
__device__ float g_V[BATCH * SEQ * DIM];
__device__ float g_Z[BATCH * SEQ];

__device__ __nv_bfloat16 g_Xh[BATCH * SEQ * DIM],  g_Xl[BATCH * SEQ * DIM];
__device__ __nv_bfloat16 g_Wh[3 * DIM * DIM],      g_Wl[3 * DIM * DIM];
__device__ __nv_bfloat16 g_Qh[BATCH * SEQ * DIM],  g_Ql[BATCH * SEQ * DIM];
__device__ __nv_bfloat16 g_Kh[BATCH * SEQ * DIM],  g_Kl[BATCH * SEQ * DIM];
__device__ __nv_bfloat16 g_VTh[BATCH * DIM * SEQ], g_VTl[BATCH * DIM * SEQ];
__device__ __nv_bfloat16 g_Eh[BATCH * SEQ * SEQ],  g_El[BATCH * SEQ * SEQ];

__device__ __forceinline__ void split2(float x, __nv_bfloat16& h, __nv_bfloat16& l)
{
    h = __float2bfloat16(x);
    l = __float2bfloat16(x - __bfloat162float(h));
}

// ===========================================================================
// GEMM mainloop: acc[2][8][4] += A[128,k] * B[128,k]^T over ktot, bf16 hi/lo
// split (hh + hl + lh). A/B K-major rows (stride lda/ldb). 256 thr, 8 warps
// (4x2), warp tile 32x64, cp.async double-buffered BK=32 stages.
// ===========================================================================
__device__ __forceinline__ void stage_mat(const __nv_bfloat16* __restrict__ src, int ld,
                                          uint32_t smb, int tid)
{
#pragma unroll
    for (int l = 0; l < 2; l++) {
        int i  = tid + l * 256;          // 0..511
        int r  = i >> 2;                 // 0..127
        int c8 = (i & 3) << 3;           // 0,8,16,24 bf16
        cp16(smb + r * (PAD_LD * 2) + c8 * 2, src + (size_t)r * ld + c8);
    }
}

__device__ __forceinline__ void mma_mainloop(
    const __nv_bfloat16* __restrict__ Ah, const __nv_bfloat16* __restrict__ Al,
    const __nv_bfloat16* __restrict__ Bh, const __nv_bfloat16* __restrict__ Bl,
    int lda, int ldb, int ktot, char* sm, float (&acc)[2][8][4])
{
    const int tid  = threadIdx.x;
    const int lane = tid & 31, warp = tid >> 5;
    const int wm = (warp >> 1) * 32;     // warp row base   (4 warps in M)
    const int wn = (warp & 1) * 64;      // warp col base   (2 warps in N)

    const uint32_t smb = smem_to_u32(sm);

    // Per-lane ldmatrix address offsets (bytes, within one 128x32 matrix)
    const uint32_t a_off = (uint32_t)(wm + (lane & 15)) * (PAD_LD * 2) + ((lane >> 4) << 4);
    const uint32_t b_off = (uint32_t)(wn + ((lane >> 4) << 3) + (lane & 7)) * (PAD_LD * 2)
                         + (((lane >> 3) & 1) << 4);

    const int nit = ktot / BK;

    // prologue: stage buffer 0
    {
        uint32_t b0 = smb;
        stage_mat(Ah, lda, b0, tid);
        stage_mat(Al, lda, b0 + MAT_BYTES, tid);
        stage_mat(Bh, ldb, b0 + 2 * MAT_BYTES, tid);
        stage_mat(Bl, ldb, b0 + 3 * MAT_BYTES, tid);
        CP_COMMIT();
    }

    for (int it = 0; it < nit; it++) {
        if (it + 1 < nit) {
            uint32_t bn = smb + ((it + 1) & 1) * 4 * MAT_BYTES;
            int k0 = (it + 1) * BK;
            stage_mat(Ah + k0, lda, bn, tid);
            stage_mat(Al + k0, lda, bn + MAT_BYTES, tid);
            stage_mat(Bh + k0, ldb, bn + 2 * MAT_BYTES, tid);
            stage_mat(Bl + k0, ldb, bn + 3 * MAT_BYTES, tid);
            CP_COMMIT();
            CP_WAIT(1);
        } else {
            CP_WAIT(0);
        }
        __syncthreads();

        const uint32_t base = smb + (it & 1) * 4 * MAT_BYTES;

#pragma unroll
        for (int ks = 0; ks < 2; ks++) {
            const uint32_t koff = (uint32_t)ks * 32;   // 16 bf16 = 32B
            uint32_t ah[2][4], al[2][4], bh[4][4], bl[4][4];
#pragma unroll
            for (int mt = 0; mt < 2; mt++) {
                uint32_t ao = a_off + (uint32_t)mt * 16 * (PAD_LD * 2) + koff;
                ldm_x4(base + ao, ah[mt]);
                ldm_x4(base + MAT_BYTES + ao, al[mt]);
            }
#pragma unroll
            for (int p = 0; p < 4; p++) {
                uint32_t bo = b_off + (uint32_t)p * 16 * (PAD_LD * 2) + koff;
                ldm_x4(base + 2 * MAT_BYTES + bo, bh[p]);
                ldm_x4(base + 3 * MAT_BYTES + bo, bl[p]);
            }
#pragma unroll
            for (int mt = 0; mt < 2; mt++)
#pragma unroll
                for (int nt = 0; nt < 8; nt++) {
                    const int p = nt >> 1, i = (nt & 1) << 1;
                    mma16816(acc[mt][nt], ah[mt], bh[p][i], bh[p][i + 1]);
                    mma16816(acc[mt][nt], ah[mt], bl[p][i], bl[p][i + 1]);
                    mma16816(acc[mt][nt], al[mt], bh[p][i], bh[p][i + 1]);
                }
        }
        __syncthreads();
    }
}

// ===========================================================================
// 0) fp32 -> bf16 hi/lo splits of X, Wq, Wk, Wv
// ===========================================================================
__global__ void split_kernel(const float* __restrict__ src, int which, int n)
{
    __nv_bfloat16 *h, *l;
    switch (which) {
        case 0:  h = g_Xh;                 l = g_Xl;                 break;
        case 1:  h = g_Wh;                 l = g_Wl;                 break;
        case 2:  h = g_Wh + DIM * DIM;     l = g_Wl + DIM * DIM;     break;
        default: h = g_Wh + 2 * DIM * DIM; l = g_Wl + 2 * DIM * DIM; break;
    }
    for (int i = blockIdx.x * blockDim.x + threadIdx.x; i < n; i += gridDim.x * blockDim.x)
        split2(src[i], h[i], l[i]);
}

// ===========================================================================
// 1) QKV projection: C = X * W^T  -> g_Q / g_K / g_V (fp32)
// ===========================================================================
__global__ __launch_bounds__(256) void gemm_qkv_mma()
{
    extern __shared__ char sm[];
    const int n0 = blockIdx.x * 128, m0 = blockIdx.y * 128, z = blockIdx.z;
    const int lane = threadIdx.x & 31, warp = threadIdx.x >> 5;
    const int wm = (warp >> 1) * 32, wn = (warp & 1) * 64;

    float acc[2][8][4] = {};
    mma_mainloop(g_Xh + (size_t)m0 * DIM, g_Xl + (size_t)m0 * DIM,
                 g_Wh + (size_t)z * DIM * DIM + (size_t)n0 * DIM,
                 g_Wl + (size_t)z * DIM * DIM + (size_t)n0 * DIM,
                 DIM, DIM, DIM, sm, acc);

    float* C = (z == 0) ? g_Q : (z == 1) ? g_K : g_V;
#pragma unroll
    for (int mt = 0; mt < 2; mt++)
#pragma unroll
        for (int nt = 0; nt < 8; nt++) {
            int r = m0 + wm + mt * 16 + (lane >> 2);
            int c = n0 + wn + nt * 8 + ((lane & 3) << 1);
            *(float2*)(C + (size_t)r * DIM + c)       = make_float2(acc[mt][nt][0], acc[mt][nt][1]);
            *(float2*)(C + (size_t)(r + 8) * DIM + c) = make_float2(acc[mt][nt][2], acc[mt][nt][3]);
        }
}

// ===========================================================================
// 2) RoPE on Q,K + bf16 hi/lo split
// ===========================================================================
__global__ void rope_split_kernel(const float* __restrict__ cosp, const float* __restrict__ sinp)
{
    int idx = blockIdx.x * blockDim.x + threadIdx.x;   // BATCH*SEQ*(DIM/2)
    int d  = idx & (DIM / 2 - 1);
    int bs = idx >> 10;
    int s  = bs & (SEQ - 1);

    float c1 = cosp[s * DIM + d];
    float s1 = sinp[s * DIM + d];
    float c2 = cosp[s * DIM + d + DIM / 2];
    float s2 = sinp[s * DIM + d + DIM / 2];

    size_t base = (size_t)bs * DIM;

    float q1 = g_Q[base + d], q2 = g_Q[base + d + DIM / 2];
    split2(q1 * c1 - q2 * s1, g_Qh[base + d],           g_Ql[base + d]);
    split2(q2 * c2 + q1 * s2, g_Qh[base + d + DIM / 2], g_Ql[base + d + DIM / 2]);

    float k1 = g_K[base + d], k2 = g_K[base + d + DIM / 2];
    split2(k1 * c1 - k2 * s1, g_Kh[base + d],           g_Kl[base + d]);
    split2(k2 * c2 + k1 * s2, g_Kh[base + d + DIM / 2], g_Kl[base + d + DIM / 2]);
}

// ===========================================================================
// 3) V transpose + split: g_V [B,S,D] fp32 -> g_VTh/l [B,D,S] bf16
// ===========================================================================
__global__ void vtrans_kernel()
{
    __shared__ float t[32][33];
    const int b = blockIdx.z;
    const int t0 = blockIdx.x * 32, d0 = blockIdx.y * 32;
    const int tx = threadIdx.x, ty = threadIdx.y;

#pragma unroll
    for (int i = 0; i < 4; i++)
        t[ty + i * 8][tx] = g_V[(size_t)b * SEQ * DIM + (size_t)(t0 + ty + i * 8) * DIM + d0 + tx];
    __syncthreads();
#pragma unroll
    for (int i = 0; i < 4; i++) {
        size_t o = (size_t)b * DIM * SEQ + (size_t)(d0 + ty + i * 8) * SEQ + t0 + tx;
        split2(t[tx][ty + i * 8], g_VTh[o], g_VTl[o]);
    }
}

// ===========================================================================
// 4) Logits: E = (t<=s) ? exp((q.k)/sqrt(S)) : 1  -> Eh/El bf16
//    Multiplicative-mask quirk: masked logits 0 -> exp(0)=1 stays in softmax
//    numerator AND the value mixing. Upper blocks skip the GEMM entirely.
// ===========================================================================
__global__ __launch_bounds__(256) void gemm_logits_mma()
{
    const int b  = blockIdx.z;
    const int n0 = blockIdx.x * 128, m0 = blockIdx.y * 128;

    __nv_bfloat16* Eh = g_Eh + (size_t)b * SEQ * SEQ;
    __nv_bfloat16* El = g_El + (size_t)b * SEQ * SEQ;

    if (n0 > m0) {  // strictly above diagonal: all ones (hi=1, lo=0)
        if (threadIdx.x < 128) {
            const uint32_t one2 = 0x3F803F80u;
            uint4 ones = make_uint4(one2, one2, one2, one2);
            uint4 zero = make_uint4(0u, 0u, 0u, 0u);
            uint4* ph = (uint4*)(Eh + (size_t)(m0 + threadIdx.x) * SEQ + n0);
            uint4* pl = (uint4*)(El + (size_t)(m0 + threadIdx.x) * SEQ + n0);
#pragma unroll
            for (int j = 0; j < 16; j++) { ph[j] = ones; pl[j] = zero; }
        }
        return;
    }

    extern __shared__ char sm[];
    const int lane = threadIdx.x & 31, warp = threadIdx.x >> 5;
    const int wm = (warp >> 1) * 32, wn = (warp & 1) * 64;

    const size_t boff = (size_t)b * SEQ * DIM;
    float acc[2][8][4] = {};
    mma_mainloop(g_Qh + boff + (size_t)m0 * DIM, g_Ql + boff + (size_t)m0 * DIM,
                 g_Kh + boff + (size_t)n0 * DIM, g_Kl + boff + (size_t)n0 * DIM,
                 DIM, DIM, DIM, sm, acc);

    const float invsq = 0.022097086912079608f;  // 1/sqrt(2048)
#pragma unroll
    for (int mt = 0; mt < 2; mt++)
#pragma unroll
        for (int nt = 0; nt < 8; nt++) {
            int c = n0 + wn + nt * 8 + ((lane & 3) << 1);
#pragma unroll
            for (int h = 0; h < 2; h++) {
                int r = m0 + wm + mt * 16 + (lane >> 2) + h * 8;
                float e0 = (c     <= r) ? __expf(acc[mt][nt][2 * h]     * invsq) : 1.0f;
                float e1 = (c + 1 <= r) ? __expf(acc[mt][nt][2 * h + 1] * invsq) : 1.0f;
                __nv_bfloat16 h0, l0, h1, l1;
                split2(e0, h0, l0);
                split2(e1, h1, l1);
                *(__nv_bfloat162*)(Eh + (size_t)r * SEQ + c) = __nv_bfloat162(h0, h1);
                *(__nv_bfloat162*)(El + (size_t)r * SEQ + c) = __nv_bfloat162(l0, l1);
            }
        }
}

// ===========================================================================
// 5) Row sums of E (=Eh+El) -> g_Z
// ===========================================================================
__global__ void rowsum_kernel()
{
    int row = blockIdx.x;                      // 0..BATCH*SEQ-1
    const __nv_bfloat16* eh = g_Eh + (size_t)row * SEQ;
    const __nv_bfloat16* el = g_El + (size_t)row * SEQ;

    float s = 0.f;
    for (int t = threadIdx.x; t < SEQ; t += 256)
        s += __bfloat162float(eh[t]) + __bfloat162float(el[t]);

#pragma unroll
    for (int o = 16; o > 0; o >>= 1) s += __shfl_xor_sync(0xffffffffu, s, o);

    __shared__ float red[8];
    int w = threadIdx.x >> 5, lane = threadIdx.x & 31;
    if (lane == 0) red[w] = s;
    __syncthreads();
    if (threadIdx.x == 0) {
        float t = 0.f;
#pragma unroll
        for (int i = 0; i < 8; i++) t += red[i];
        g_Z[row] = t;
    }
}

// ===========================================================================
// 6) PV: out[b,s,d] = (sum_t E[s,t] * VT[d,t]) / Z[b,s]
// ===========================================================================
__global__ __launch_bounds__(256) void gemm_pv_mma(float* __restrict__ out)
{
    extern __shared__ char sm[];
    const int b  = blockIdx.z;
    const int n0 = blockIdx.x * 128, m0 = blockIdx.y * 128;
    const int lane = threadIdx.x & 31, warp = threadIdx.x >> 5;
    const int wm = (warp >> 1) * 32, wn = (warp & 1) * 64;

    float acc[2][8][4] = {};
    mma_mainloop(g_Eh  + (size_t)b * SEQ * SEQ + (size_t)m0 * SEQ,
                 g_El  + (size_t)b * SEQ * SEQ + (size_t)m0 * SEQ,
                 g_VTh + (size_t)b * DIM * SEQ + (size_t)n0 * SEQ,
                 g_VTl + (size_t)b * DIM * SEQ + (size_t)n0 * SEQ,
                 SEQ, SEQ, SEQ, sm, acc);

#pragma unroll
    for (int mt = 0; mt < 2; mt++)
#pragma unroll
        for (int nt = 0; nt < 8; nt++) {
            int r = m0 + wm + mt * 16 + (lane >> 2);
            int c = n0 + wn + nt * 8 + ((lane & 3) << 1);
            float ri0 = 1.0f / g_Z[b * SEQ + r];
            float ri1 = 1.0f / g_Z[b * SEQ + r + 8];
            float* o0 = out + (size_t)b * SEQ * DIM + (size_t)r * DIM + c;
            float* o1 = out + (size_t)b * SEQ * DIM + (size_t)(r + 8) * DIM + c;
            *(float2*)o0 = make_float2(acc[mt][nt][0] * ri0, acc[mt][nt][1] * ri0);
            *(float2*)o1 = make_float2(acc[mt][nt][2] * ri1, acc[mt][nt][3] * ri1);
        }
}

// ===========================================================================
// Launch: x, cos, sin, Wq, Wk, Wv  ->  out [B,S,D] fp32
// ===========================================================================
extern "C" void kernel_launch(void* const* d_in, const int* in_sizes, int n_in,
                              void* d_out, int out_size)
{
    const float* x    = (const float*)d_in[0];
    const float* cosp = (const float*)d_in[1];
    const float* sinp = (const float*)d_in[2];
    const float* Wq   = (const float*)d_in[3];
    const float* Wk   = (const float*)d_in[4];
    const float* Wv   = (const float*)d_in[5];
    float* out = (float*)d_out;

    (void)in_sizes; (void)n_in; (void)out_size;

    cudaFuncSetAttribute(gemm_qkv_mma,    cudaFuncAttributeMaxDynamicSharedMemorySize, SMEM_DYN_BYTES);
    cudaFuncSetAttribute(gemm_logits_mma, cudaFuncAttributeMaxDynamicSharedMemorySize, SMEM_DYN_BYTES);
    cudaFuncSetAttribute(gemm_pv_mma,     cudaFuncAttributeMaxDynamicSharedMemorySize, SMEM_DYN_BYTES);

    split_kernel<<<(BATCH * SEQ * DIM) / 256, 256>>>(x, 0, BATCH * SEQ * DIM);
    split_kernel<<<(DIM * DIM) / 256, 256>>>(Wq, 1, DIM * DIM);
    split_kernel<<<(DIM * DIM) / 256, 256>>>(Wk, 2, DIM * DIM);
    split_kernel<<<(DIM * DIM) / 256, 256>>>(Wv, 3, DIM * DIM);

    gemm_qkv_mma<<<dim3(DIM / 128, (BATCH * SEQ) / 128, 3), 256, SMEM_DYN_BYTES>>>();
    rope_split_kernel<<<(BATCH * SEQ * (DIM / 2)) / 256, 256>>>(cosp, sinp);
    vtrans_kernel<<<dim3(SEQ / 32, DIM / 32, BATCH), dim3(32, 8)>>>();
    gemm_logits_mma<<<dim3(SEQ / 128, SEQ / 128, BATCH), 256, SMEM_DYN_BYTES>>>();
    rowsum_kernel<<<BATCH * SEQ, 256>>>();
    gemm_pv_mma<<<dim3(DIM / 128, SEQ / 128, BATCH), 256, SMEM_DYN_BYTES>>>(out);
}

// round 6
// speedup vs baseline: 2.7574x; 1.0655x over previous
#include <cuda_runtime.h>
#include <cuda_bf16.h>
#include <stdint.h>
#include <math.h>

#define BATCH 4
#define SEQ   2048
#define DIM   2048

#define BK 32
#define PAD_LD 40                         // bf16 per smem row (80B, conflict-free for ldmatrix)
#define MAT_BYTES (128 * PAD_LD * 2)      // 10240 B per 128x32 matrix
#define SMEM_DYN_BYTES (2 * 4 * MAT_BYTES)  // 2 buffers x (Ah,Al,Bh,Bl) = 81920 B

// ===========================================================================
// PTX helpers (sm_80-era: valid under compute_100)
// ===========================================================================
__device__ __forceinline__ uint32_t smem_to_u32(const void* p) {
    uint32_t a;
    asm("{ .reg .u64 t; cvta.to.shared.u64 t, %1; cvt.u32.u64 %0, t; }" : "=r"(a) : "l"(p));
    return a;
}

__device__ __forceinline__ void cp16(uint32_t dst, const void* src) {
    asm volatile("cp.async.cg.shared.global [%0], [%1], 16;" :: "r"(dst), "l"(src) : "memory");
}
#define CP_COMMIT()  asm volatile("cp.async.commit_group;" ::: "memory")
#define CP_WAIT(n)   asm volatile("cp.async.wait_group %0;" :: "n"(n) : "memory")

__device__ __forceinline__ void ldm_x4(uint32_t addr, uint32_t (&r)[4]) {
    asm volatile("ldmatrix.sync.aligned.m8n8.x4.shared.b16 {%0,%1,%2,%3}, [%4];"
                 : "=r"(r[0]), "=r"(r[1]), "=r"(r[2]), "=r"(r[3]) : "r"(addr));
}

__device__ __forceinline__ void mma16816(float (&c)[4], const uint32_t (&a)[4],
                                         uint32_t b0, uint32_t b1) {
    asm volatile("mma.sync.aligned.m16n8k16.row.col.f32.bf16.bf16.f32 "
                 "{%0,%1,%2,%3}, {%4,%5,%6,%7}, {%8,%9}, {%0,%1,%2,%3};"
                 : "+f"(c[0]), "+f"(c[1]), "+f"(c[2]), "+f"(c[3])
                 : "r"(a[0]), "r"(a[1]), "r"(a[2]), "r"(a[3]), "r"(b0), "r"(b1));
}

// ===========================================================================
// Scratch (allocation-free rule: static __device__ arrays)
// ===========================================================================
__device__ float g_Q[BATCH * SEQ * DIM];
__device__ float g_K[BATCH * SEQ * DIM];
__device__ float g_V[BATCH * SEQ * DIM];
__device__ float g_Z[BATCH * SEQ];
__device__ float g_P[BATCH * 16 * DIM];          // per-128-block column sums of V
__device__ float g_T[BATCH * 17 * DIM];          // suffix sums; T[b][16][d] = 0

__device__ __nv_bfloat16 g_Xh[BATCH * SEQ * DIM],  g_Xl[BATCH * SEQ * DIM];
__device__ __nv_bfloat16 g_Wh[3 * DIM * DIM],      g_Wl[3 * DIM * DIM];
__device__ __nv_bfloat16 g_Qh[BATCH * SEQ * DIM],  g_Ql[BATCH * SEQ * DIM];
__device__ __nv_bfloat16 g_Kh[BATCH * SEQ * DIM],  g_Kl[BATCH * SEQ * DIM];
__device__ __nv_bfloat16 g_VTh[BATCH * DIM * SEQ], g_VTl[BATCH * DIM * SEQ];
__device__ __nv_bfloat16 g_Eh[BATCH * SEQ * SEQ],  g_El[BATCH * SEQ * SEQ];

__device__ __forceinline__ void split2(float x, __nv_bfloat16& h, __nv_bfloat16& l)
{
    h = __float2bfloat16(x);
    l = __float2bfloat16(x - __bfloat162float(h));
}

// ===========================================================================
// GEMM mainloop: acc[2][8][4] += A[128,k] * B[128,k]^T over ktot, bf16 hi/lo
// split (hh + hl + lh). A/B K-major rows (stride lda/ldb). 256 thr, 8 warps
// (4x2), warp tile 32x64, cp.async double-buffered BK=32 stages.
// ===========================================================================
__device__ __forceinline__ void stage_mat(const __nv_bfloat16* __restrict__ src, int ld,
                                          uint32_t smb, int tid)
{
#pragma unroll
    for (int l = 0; l < 2; l++) {
        int i  = tid + l * 256;          // 0..511
        int r  = i >> 2;                 // 0..127
        int c8 = (i & 3) << 3;           // 0,8,16,24 bf16
        cp16(smb + r * (PAD_LD * 2) + c8 * 2, src + (size_t)r * ld + c8);
    }
}

__device__ __forceinline__ void mma_mainloop(
    const __nv_bfloat16* __restrict__ Ah, const __nv_bfloat16* __restrict__ Al,
    const __nv_bfloat16* __restrict__ Bh, const __nv_bfloat16* __restrict__ Bl,
    int lda, int ldb, int ktot, char* sm, float (&acc)[2][8][4])
{
    const int tid  = threadIdx.x;
    const int lane = tid & 31, warp = tid >> 5;
    const int wm = (warp >> 1) * 32;     // warp row base   (4 warps in M)
    const int wn = (warp & 1) * 64;      // warp col base   (2 warps in N)

    const uint32_t smb = smem_to_u32(sm);

    // Per-lane ldmatrix address offsets (bytes, within one 128x32 matrix)
    const uint32_t a_off = (uint32_t)(wm + (lane & 15)) * (PAD_LD * 2) + ((lane >> 4) << 4);
    const uint32_t b_off = (uint32_t)(wn + ((lane >> 4) << 3) + (lane & 7)) * (PAD_LD * 2)
                         + (((lane >> 3) & 1) << 4);

    const int nit = ktot / BK;

    // prologue: stage buffer 0
    {
        uint32_t b0 = smb;
        stage_mat(Ah, lda, b0, tid);
        stage_mat(Al, lda, b0 + MAT_BYTES, tid);
        stage_mat(Bh, ldb, b0 + 2 * MAT_BYTES, tid);
        stage_mat(Bl, ldb, b0 + 3 * MAT_BYTES, tid);
        CP_COMMIT();
    }

    for (int it = 0; it < nit; it++) {
        if (it + 1 < nit) {
            uint32_t bn = smb + ((it + 1) & 1) * 4 * MAT_BYTES;
            int k0 = (it + 1) * BK;
            stage_mat(Ah + k0, lda, bn, tid);
            stage_mat(Al + k0, lda, bn + MAT_BYTES, tid);
            stage_mat(Bh + k0, ldb, bn + 2 * MAT_BYTES, tid);
            stage_mat(Bl + k0, ldb, bn + 3 * MAT_BYTES, tid);
            CP_COMMIT();
            CP_WAIT(1);
        } else {
            CP_WAIT(0);
        }
        __syncthreads();

        const uint32_t base = smb + (it & 1) * 4 * MAT_BYTES;

#pragma unroll
        for (int ks = 0; ks < 2; ks++) {
            const uint32_t koff = (uint32_t)ks * 32;   // 16 bf16 = 32B
            uint32_t ah[2][4], al[2][4], bh[4][4], bl[4][4];
#pragma unroll
            for (int mt = 0; mt < 2; mt++) {
                uint32_t ao = a_off + (uint32_t)mt * 16 * (PAD_LD * 2) + koff;
                ldm_x4(base + ao, ah[mt]);
                ldm_x4(base + MAT_BYTES + ao, al[mt]);
            }
#pragma unroll
            for (int p = 0; p < 4; p++) {
                uint32_t bo = b_off + (uint32_t)p * 16 * (PAD_LD * 2) + koff;
                ldm_x4(base + 2 * MAT_BYTES + bo, bh[p]);
                ldm_x4(base + 3 * MAT_BYTES + bo, bl[p]);
            }
#pragma unroll
            for (int mt = 0; mt < 2; mt++)
#pragma unroll
                for (int nt = 0; nt < 8; nt++) {
                    const int p = nt >> 1, i = (nt & 1) << 1;
                    mma16816(acc[mt][nt], ah[mt], bh[p][i], bh[p][i + 1]);
                    mma16816(acc[mt][nt], ah[mt], bl[p][i], bl[p][i + 1]);
                    mma16816(acc[mt][nt], al[mt], bh[p][i], bh[p][i + 1]);
                }
        }
        __syncthreads();
    }
}

// ===========================================================================
// 0) fp32 -> bf16 hi/lo splits of X, Wq, Wk, Wv
// ===========================================================================
__global__ void split_kernel(const float* __restrict__ src, int which, int n)
{
    __nv_bfloat16 *h, *l;
    switch (which) {
        case 0:  h = g_Xh;                 l = g_Xl;                 break;
        case 1:  h = g_Wh;                 l = g_Wl;                 break;
        case 2:  h = g_Wh + DIM * DIM;     l = g_Wl + DIM * DIM;     break;
        default: h = g_Wh + 2 * DIM * DIM; l = g_Wl + 2 * DIM * DIM; break;
    }
    for (int i = blockIdx.x * blockDim.x + threadIdx.x; i < n; i += gridDim.x * blockDim.x)
        split2(src[i], h[i], l[i]);
}

// ===========================================================================
// 1) QKV projection: C = X * W^T  -> g_Q / g_K / g_V (fp32)
// ===========================================================================
__global__ __launch_bounds__(256) void gemm_qkv_mma()
{
    extern __shared__ char sm[];
    const int n0 = blockIdx.x * 128, m0 = blockIdx.y * 128, z = blockIdx.z;
    const int lane = threadIdx.x & 31, warp = threadIdx.x >> 5;
    const int wm = (warp >> 1) * 32, wn = (warp & 1) * 64;

    float acc[2][8][4] = {};
    mma_mainloop(g_Xh + (size_t)m0 * DIM, g_Xl + (size_t)m0 * DIM,
                 g_Wh + (size_t)z * DIM * DIM + (size_t)n0 * DIM,
                 g_Wl + (size_t)z * DIM * DIM + (size_t)n0 * DIM,
                 DIM, DIM, DIM, sm, acc);

    float* C = (z == 0) ? g_Q : (z == 1) ? g_K : g_V;
#pragma unroll
    for (int mt = 0; mt < 2; mt++)
#pragma unroll
        for (int nt = 0; nt < 8; nt++) {
            int r = m0 + wm + mt * 16 + (lane >> 2);
            int c = n0 + wn + nt * 8 + ((lane & 3) << 1);
            *(float2*)(C + (size_t)r * DIM + c)       = make_float2(acc[mt][nt][0], acc[mt][nt][1]);
            *(float2*)(C + (size_t)(r + 8) * DIM + c) = make_float2(acc[mt][nt][2], acc[mt][nt][3]);
        }
}

// ===========================================================================
// 2) RoPE on Q,K + bf16 hi/lo split
// ===========================================================================
__global__ void rope_split_kernel(const float* __restrict__ cosp, const float* __restrict__ sinp)
{
    int idx = blockIdx.x * blockDim.x + threadIdx.x;   // BATCH*SEQ*(DIM/2)
    int d  = idx & (DIM / 2 - 1);
    int bs = idx >> 10;
    int s  = bs & (SEQ - 1);

    float c1 = cosp[s * DIM + d];
    float s1 = sinp[s * DIM + d];
    float c2 = cosp[s * DIM + d + DIM / 2];
    float s2 = sinp[s * DIM + d + DIM / 2];

    size_t base = (size_t)bs * DIM;

    float q1 = g_Q[base + d], q2 = g_Q[base + d + DIM / 2];
    split2(q1 * c1 - q2 * s1, g_Qh[base + d],           g_Ql[base + d]);
    split2(q2 * c2 + q1 * s2, g_Qh[base + d + DIM / 2], g_Ql[base + d + DIM / 2]);

    float k1 = g_K[base + d], k2 = g_K[base + d + DIM / 2];
    split2(k1 * c1 - k2 * s1, g_Kh[base + d],           g_Kl[base + d]);
    split2(k2 * c2 + k1 * s2, g_Kh[base + d + DIM / 2], g_Kl[base + d + DIM / 2]);
}

// ===========================================================================
// 3) V transpose + split: g_V [B,S,D] fp32 -> g_VTh/l [B,D,S] bf16
// ===========================================================================
__global__ void vtrans_kernel()
{
    __shared__ float t[32][33];
    const int b = blockIdx.z;
    const int t0 = blockIdx.x * 32, d0 = blockIdx.y * 32;
    const int tx = threadIdx.x, ty = threadIdx.y;

#pragma unroll
    for (int i = 0; i < 4; i++)
        t[ty + i * 8][tx] = g_V[(size_t)b * SEQ * DIM + (size_t)(t0 + ty + i * 8) * DIM + d0 + tx];
    __syncthreads();
#pragma unroll
    for (int i = 0; i < 4; i++) {
        size_t o = (size_t)b * DIM * SEQ + (size_t)(d0 + ty + i * 8) * SEQ + t0 + tx;
        split2(t[tx][ty + i * 8], g_VTh[o], g_VTl[o]);
    }
}

// ===========================================================================
// 3b) Block column sums of V: P[b][i][d] = sum_{t in block i} V[b][t][d]
// ===========================================================================
__global__ void pv_blocksum_kernel()
{
    const int b = blockIdx.z, i = blockIdx.y;
    const int d = blockIdx.x * 256 + threadIdx.x;
    const float* v = g_V + (size_t)b * SEQ * DIM + (size_t)i * 128 * DIM + d;
    float s = 0.f;
#pragma unroll 8
    for (int k = 0; k < 128; k++) s += v[(size_t)k * DIM];
    g_P[((size_t)b * 16 + i) * DIM + d] = s;
}

// 3c) Suffix: T[b][j][d] = sum_{i>=j} P[b][i][d]; T[b][16][d] = 0
__global__ void pv_suffix_kernel()
{
    const int b = blockIdx.y;
    const int d = blockIdx.x * 256 + threadIdx.x;
    float acc = 0.f;
    g_T[((size_t)b * 17 + 16) * DIM + d] = 0.f;
#pragma unroll
    for (int i = 15; i >= 0; i--) {
        acc += g_P[((size_t)b * 16 + i) * DIM + d];
        g_T[((size_t)b * 17 + i) * DIM + d] = acc;
    }
}

// ===========================================================================
// 4) Logits: E = (t<=s) ? exp((q.k)/sqrt(S)) : 1  -> Eh/El bf16
//    Multiplicative-mask quirk: masked logits 0 -> exp(0)=1 stays in softmax
//    numerator AND the value mixing. Upper-triangle BLOCKS are never written:
//    rowsum adds their count analytically; PV uses suffix sums g_T instead.
// ===========================================================================
__global__ __launch_bounds__(256) void gemm_logits_mma()
{
    const int b  = blockIdx.z;
    const int n0 = blockIdx.x * 128, m0 = blockIdx.y * 128;

    if (n0 > m0) return;  // strictly above diagonal: not materialized

    __nv_bfloat16* Eh = g_Eh + (size_t)b * SEQ * SEQ;
    __nv_bfloat16* El = g_El + (size_t)b * SEQ * SEQ;

    extern __shared__ char sm[];
    const int lane = threadIdx.x & 31, warp = threadIdx.x >> 5;
    const int wm = (warp >> 1) * 32, wn = (warp & 1) * 64;

    const size_t boff = (size_t)b * SEQ * DIM;
    float acc[2][8][4] = {};
    mma_mainloop(g_Qh + boff + (size_t)m0 * DIM, g_Ql + boff + (size_t)m0 * DIM,
                 g_Kh + boff + (size_t)n0 * DIM, g_Kl + boff + (size_t)n0 * DIM,
                 DIM, DIM, DIM, sm, acc);

    const float invsq = 0.022097086912079608f;  // 1/sqrt(2048)
#pragma unroll
    for (int mt = 0; mt < 2; mt++)
#pragma unroll
        for (int nt = 0; nt < 8; nt++) {
            int c = n0 + wn + nt * 8 + ((lane & 3) << 1);
#pragma unroll
            for (int h = 0; h < 2; h++) {
                int r = m0 + wm + mt * 16 + (lane >> 2) + h * 8;
                float e0 = (c     <= r) ? __expf(acc[mt][nt][2 * h]     * invsq) : 1.0f;
                float e1 = (c + 1 <= r) ? __expf(acc[mt][nt][2 * h + 1] * invsq) : 1.0f;
                __nv_bfloat16 h0, l0, h1, l1;
                split2(e0, h0, l0);
                split2(e1, h1, l1);
                *(__nv_bfloat162*)(Eh + (size_t)r * SEQ + c) = __nv_bfloat162(h0, h1);
                *(__nv_bfloat162*)(El + (size_t)r * SEQ + c) = __nv_bfloat162(l0, l1);
            }
        }
}

// ===========================================================================
// 5) Row sums: Z[r] = sum_{t<blockend} E[r,t] + (SEQ - blockend) ones
// ===========================================================================
__global__ void rowsum_kernel()
{
    int row = blockIdx.x;                      // 0..BATCH*SEQ-1
    int r = row & (SEQ - 1);
    int blockend = ((r >> 7) + 1) << 7;        // end of diagonal 128-block
    const __nv_bfloat16* eh = g_Eh + (size_t)row * SEQ;
    const __nv_bfloat16* el = g_El + (size_t)row * SEQ;

    float s = 0.f;
    for (int t = threadIdx.x; t < blockend; t += 256)
        s += __bfloat162float(eh[t]) + __bfloat162float(el[t]);

#pragma unroll
    for (int o = 16; o > 0; o >>= 1) s += __shfl_xor_sync(0xffffffffu, s, o);

    __shared__ float red[8];
    int w = threadIdx.x >> 5, lane = threadIdx.x & 31;
    if (lane == 0) red[w] = s;
    __syncthreads();
    if (threadIdx.x == 0) {
        float t = 0.f;
#pragma unroll
        for (int i = 0; i < 8; i++) t += red[i];
        g_Z[row] = t + (float)(SEQ - blockend);
    }
}

// ===========================================================================
// 6) PV: out[b,s,d] = (sum_{t<blockend} E[s,t]*V[t,d] + T[i+1,d]) / Z[b,s]
//    Only lower+diagonal k-blocks hit the GEMM; ones-region comes from g_T.
// ===========================================================================
__global__ __launch_bounds__(256) void gemm_pv_mma(float* __restrict__ out)
{
    extern __shared__ char sm[];
    const int b  = blockIdx.z;
    const int n0 = blockIdx.x * 128, m0 = blockIdx.y * 128;
    const int lane = threadIdx.x & 31, warp = threadIdx.x >> 5;
    const int wm = (warp >> 1) * 32, wn = (warp & 1) * 64;
    const int mi = m0 >> 7;                    // m-tile index: k runs over blocks 0..mi

    float acc[2][8][4] = {};
    mma_mainloop(g_Eh  + (size_t)b * SEQ * SEQ + (size_t)m0 * SEQ,
                 g_El  + (size_t)b * SEQ * SEQ + (size_t)m0 * SEQ,
                 g_VTh + (size_t)b * DIM * SEQ + (size_t)n0 * SEQ,
                 g_VTl + (size_t)b * DIM * SEQ + (size_t)n0 * SEQ,
                 SEQ, SEQ, (mi + 1) * 128, sm, acc);

    const float* Trow = g_T + ((size_t)b * 17 + (mi + 1)) * DIM;
#pragma unroll
    for (int mt = 0; mt < 2; mt++)
#pragma unroll
        for (int nt = 0; nt < 8; nt++) {
            int r = m0 + wm + mt * 16 + (lane >> 2);
            int c = n0 + wn + nt * 8 + ((lane & 3) << 1);
            float t0 = Trow[c], t1 = Trow[c + 1];
            float ri0 = 1.0f / g_Z[b * SEQ + r];
            float ri1 = 1.0f / g_Z[b * SEQ + r + 8];
            float* o0 = out + (size_t)b * SEQ * DIM + (size_t)r * DIM + c;
            float* o1 = out + (size_t)b * SEQ * DIM + (size_t)(r + 8) * DIM + c;
            *(float2*)o0 = make_float2((acc[mt][nt][0] + t0) * ri0, (acc[mt][nt][1] + t1) * ri0);
            *(float2*)o1 = make_float2((acc[mt][nt][2] + t0) * ri1, (acc[mt][nt][3] + t1) * ri1);
        }
}

// ===========================================================================
// Launch: x, cos, sin, Wq, Wk, Wv  ->  out [B,S,D] fp32
// ===========================================================================
extern "C" void kernel_launch(void* const* d_in, const int* in_sizes, int n_in,
                              void* d_out, int out_size)
{
    const float* x    = (const float*)d_in[0];
    const float* cosp = (const float*)d_in[1];
    const float* sinp = (const float*)d_in[2];
    const float* Wq   = (const float*)d_in[3];
    const float* Wk   = (const float*)d_in[4];
    const float* Wv   = (const float*)d_in[5];
    float* out = (float*)d_out;

    (void)in_sizes; (void)n_in; (void)out_size;

    cudaFuncSetAttribute(gemm_qkv_mma,    cudaFuncAttributeMaxDynamicSharedMemorySize, SMEM_DYN_BYTES);
    cudaFuncSetAttribute(gemm_logits_mma, cudaFuncAttributeMaxDynamicSharedMemorySize, SMEM_DYN_BYTES);
    cudaFuncSetAttribute(gemm_pv_mma,     cudaFuncAttributeMaxDynamicSharedMemorySize, SMEM_DYN_BYTES);

    split_kernel<<<(BATCH * SEQ * DIM) / 256, 256>>>(x, 0, BATCH * SEQ * DIM);
    split_kernel<<<(DIM * DIM) / 256, 256>>>(Wq, 1, DIM * DIM);
    split_kernel<<<(DIM * DIM) / 256, 256>>>(Wk, 2, DIM * DIM);
    split_kernel<<<(DIM * DIM) / 256, 256>>>(Wv, 3, DIM * DIM);

    gemm_qkv_mma<<<dim3(DIM / 128, (BATCH * SEQ) / 128, 3), 256, SMEM_DYN_BYTES>>>();
    rope_split_kernel<<<(BATCH * SEQ * (DIM / 2)) / 256, 256>>>(cosp, sinp);
    vtrans_kernel<<<dim3(SEQ / 32, DIM / 32, BATCH), dim3(32, 8)>>>();
    pv_blocksum_kernel<<<dim3(DIM / 256, 16, BATCH), 256>>>();
    pv_suffix_kernel<<<dim3(DIM / 256, BATCH), 256>>>();
    gemm_logits_mma<<<dim3(SEQ / 128, SEQ / 128, BATCH), 256, SMEM_DYN_BYTES>>>();
    rowsum_kernel<<<BATCH * SEQ, 256>>>();
    gemm_pv_mma<<<dim3(DIM / 128, SEQ / 128, BATCH), 256, SMEM_DYN_BYTES>>>(out);
}